// round 4
// baseline (speedup 1.0000x reference)
#include <cuda_runtime.h>
#include <cuda_bf16.h>
#include <math.h>

// Problem constants
#define B_   4
#define S_   1500
#define E_   1280
#define H_   20
#define D_   64
#define M_   (B_ * S_)   // 6000

// Scratch buffers (device globals: allocation-free rule)
__device__ float g_q[(size_t)B_ * H_ * S_ * D_];    // [b,h,s,d]
__device__ float g_k[(size_t)B_ * H_ * S_ * D_];
__device__ float g_v[(size_t)B_ * H_ * S_ * D_];
__device__ float g_ctx[(size_t)B_ * S_ * E_];       // [b,s,(h*64+d)]

// ---------------------------------------------------------------------------
// Generic 128x128x16 SIMT fp32 GEMM:  out = A[M,K] @ W[N,K]^T  (+bias)(*scale)
// mode 0: plain row-major [M,N] out, +bias              (final projection)
// mode 1: scatter to g_q [b,h,s,d], (+bias)*scale       (q projection)
// mode 2: scatter to g_k [b,h,s,d], no bias             (k projection)
// mode 3: scatter to g_v [b,h,s,d], +bias               (v projection)
// A==nullptr means "read from g_ctx".
// ---------------------------------------------------------------------------
__global__ void gemm128(const float* __restrict__ A,
                        const float* __restrict__ W,
                        const float* __restrict__ bias,
                        float scale,
                        float* __restrict__ out,
                        int mode)
{
    const int K = E_;
    const int N = E_;
    __shared__ float As[16][128];
    __shared__ float Bs[16][128];

    const float* Ap = A ? A : g_ctx;

    int tid = threadIdx.x;
    int m0 = blockIdx.x * 128;
    int n0 = blockIdx.y * 128;
    int tx = tid & 15;          // 0..15
    int ty = tid >> 4;          // 0..15

    float acc[8][8];
#pragma unroll
    for (int i = 0; i < 8; i++)
#pragma unroll
        for (int j = 0; j < 8; j++) acc[i][j] = 0.f;

    int lr = tid >> 2;           // 0..63
    int lc4 = (tid & 3) * 4;     // 0,4,8,12

    for (int k0 = 0; k0 < K; k0 += 16) {
#pragma unroll
        for (int half = 0; half < 2; half++) {
            int row = lr + half * 64;
            int gm = m0 + row;
            float4 av = make_float4(0.f, 0.f, 0.f, 0.f);
            if (gm < M_)
                av = *(const float4*)(Ap + (size_t)gm * K + k0 + lc4);
            As[lc4 + 0][row] = av.x;
            As[lc4 + 1][row] = av.y;
            As[lc4 + 2][row] = av.z;
            As[lc4 + 3][row] = av.w;

            int gn = n0 + row;   // always < 1280
            float4 bv = *(const float4*)(W + (size_t)gn * K + k0 + lc4);
            Bs[lc4 + 0][row] = bv.x;
            Bs[lc4 + 1][row] = bv.y;
            Bs[lc4 + 2][row] = bv.z;
            Bs[lc4 + 3][row] = bv.w;
        }
        __syncthreads();

#pragma unroll
        for (int kk = 0; kk < 16; kk++) {
            float4 a0 = *(const float4*)&As[kk][ty * 8];
            float4 a1 = *(const float4*)&As[kk][ty * 8 + 4];
            float4 b0 = *(const float4*)&Bs[kk][tx * 8];
            float4 b1 = *(const float4*)&Bs[kk][tx * 8 + 4];
            float a[8] = {a0.x, a0.y, a0.z, a0.w, a1.x, a1.y, a1.z, a1.w};
            float b[8] = {b0.x, b0.y, b0.z, b0.w, b1.x, b1.y, b1.z, b1.w};
#pragma unroll
            for (int i = 0; i < 8; i++)
#pragma unroll
                for (int j = 0; j < 8; j++)
                    acc[i][j] += a[i] * b[j];
        }
        __syncthreads();
    }

    // epilogue
    float* qout = g_q;
    float* kout = g_k;
    float* vout = g_v;
#pragma unroll
    for (int i = 0; i < 8; i++) {
        int gm = m0 + ty * 8 + i;
        if (gm >= M_) continue;
        int b = gm / S_;
        int s = gm % S_;
#pragma unroll
        for (int j = 0; j < 8; j++) {
            int gn = n0 + tx * 8 + j;
            float v = acc[i][j];
            if (mode == 0) {
                out[(size_t)gm * N + gn] = v + bias[gn];
            } else {
                if (mode == 1) v = (v + bias[gn]) * scale;
                else if (mode == 3) v = v + bias[gn];
                int h = gn >> 6;
                int d = gn & 63;
                size_t idx = ((((size_t)b * H_ + h) * S_) + s) * D_ + d;
                if (mode == 1) qout[idx] = v;
                else if (mode == 2) kout[idx] = v;
                else vout[idx] = v;
            }
        }
    }
}

// ---------------------------------------------------------------------------
// Flash attention: grid (qblocks=24, bh=80), 256 threads.
// 64 query rows x 64 key cols per tile; online softmax; context written in
// [b, s, h*64+d] layout so the output GEMM reads it row-major.
// Shared tiles padded to stride 68 floats => all inner-loop LDS.128
// conflict-free, and 16B-aligned rows.
// ---------------------------------------------------------------------------
#define PAD 68
#define ATTN_SMEM (4 * 64 * PAD * 4)   // 69632 bytes

__global__ void attn_kernel(const float* __restrict__ mask)
{
    extern __shared__ float sm[];
    float* Qs = sm;                     // [64][68]
    float* Ks = sm + 64 * PAD;
    float* Vs = sm + 2 * 64 * PAD;
    float* Ps = sm + 3 * 64 * PAD;

    int bh = blockIdx.y;
    int b = bh / H_;
    int h = bh % H_;
    int qb = blockIdx.x;
    int tid = threadIdx.x;
    int i = tid >> 2;      // query row within tile, 0..63
    int c = tid & 3;       // 0..3

    const float* qbase = g_q + (((size_t)b * H_ + h) * S_) * D_;
    const float* kbase = g_k + (((size_t)b * H_ + h) * S_) * D_;
    const float* vbase = g_v + (((size_t)b * H_ + h) * S_) * D_;

    // load Q tile
    {
        int lr = tid >> 4;           // 0..15
        int lc = (tid & 15) * 4;     // 0..60
        for (int r = lr; r < 64; r += 16) {
            int sq = qb * 64 + r;
            float4 val = make_float4(0.f, 0.f, 0.f, 0.f);
            if (sq < S_)
                val = *(const float4*)(qbase + (size_t)sq * D_ + lc);
            Qs[r * PAD + lc + 0] = val.x;
            Qs[r * PAD + lc + 1] = val.y;
            Qs[r * PAD + lc + 2] = val.z;
            Qs[r * PAD + lc + 3] = val.w;
        }
    }

    float4 acc4[4];
#pragma unroll
    for (int t = 0; t < 4; t++) acc4[t] = make_float4(0.f, 0.f, 0.f, 0.f);
    float m_i = -1e30f, l_i = 0.f;

    int sq = qb * 64 + i;
    const float* mrow = mask + ((size_t)b * S_ + (sq < S_ ? sq : S_ - 1)) * S_;

    const int nkb = (S_ + 63) / 64;   // 24
    for (int kb = 0; kb < nkb; kb++) {
        // load K/V tiles
        {
            int lr = tid >> 4;
            int lc = (tid & 15) * 4;
            for (int r = lr; r < 64; r += 16) {
                int sk = kb * 64 + r;
                float4 kv = make_float4(0.f, 0.f, 0.f, 0.f);
                float4 vv = make_float4(0.f, 0.f, 0.f, 0.f);
                if (sk < S_) {
                    kv = *(const float4*)(kbase + (size_t)sk * D_ + lc);
                    vv = *(const float4*)(vbase + (size_t)sk * D_ + lc);
                }
                Ks[r * PAD + lc + 0] = kv.x; Ks[r * PAD + lc + 1] = kv.y;
                Ks[r * PAD + lc + 2] = kv.z; Ks[r * PAD + lc + 3] = kv.w;
                Vs[r * PAD + lc + 0] = vv.x; Vs[r * PAD + lc + 1] = vv.y;
                Vs[r * PAD + lc + 2] = vv.z; Vs[r * PAD + lc + 3] = vv.w;
            }
        }
        __syncthreads();

        // scores: thread (i,c) computes keys j = jj*4 + c, jj = 0..15
        float sc[16];
#pragma unroll
        for (int jj = 0; jj < 16; jj++) sc[jj] = 0.f;
#pragma unroll
        for (int d4 = 0; d4 < 16; d4++) {
            float4 qa = *(const float4*)&Qs[i * PAD + d4 * 4];
#pragma unroll
            for (int jj = 0; jj < 16; jj++) {
                float4 kk4 = *(const float4*)&Ks[(jj * 4 + c) * PAD + d4 * 4];
                sc[jj] += qa.x * kk4.x + qa.y * kk4.y + qa.z * kk4.z + qa.w * kk4.w;
            }
        }
        // add mask / bound keys
#pragma unroll
        for (int jj = 0; jj < 16; jj++) {
            int sk = kb * 64 + jj * 4 + c;
            sc[jj] = (sk < S_) ? (sc[jj] + mrow[sk]) : -1e30f;
        }

        // online softmax (row groups of 4 lanes)
        float rmax = sc[0];
#pragma unroll
        for (int jj = 1; jj < 16; jj++) rmax = fmaxf(rmax, sc[jj]);
        rmax = fmaxf(rmax, __shfl_xor_sync(0xffffffffu, rmax, 1));
        rmax = fmaxf(rmax, __shfl_xor_sync(0xffffffffu, rmax, 2));
        float mnew = fmaxf(m_i, rmax);
        float corr = __expf(m_i - mnew);
        float rsum = 0.f;
#pragma unroll
        for (int jj = 0; jj < 16; jj++) {
            float p = __expf(sc[jj] - mnew);
            Ps[i * PAD + jj * 4 + c] = p;
            rsum += p;
        }
        rsum += __shfl_xor_sync(0xffffffffu, rsum, 1);
        rsum += __shfl_xor_sync(0xffffffffu, rsum, 2);
        l_i = l_i * corr + rsum;
        m_i = mnew;
#pragma unroll
        for (int t = 0; t < 4; t++) {
            acc4[t].x *= corr; acc4[t].y *= corr;
            acc4[t].z *= corr; acc4[t].w *= corr;
        }
        __syncthreads();

        // AV: thread (i,c) owns d-chunks (t*4+c)*4 .. +3
        for (int j = 0; j < 64; j++) {
            float p = Ps[i * PAD + j];
#pragma unroll
            for (int t = 0; t < 4; t++) {
                float4 vv = *(const float4*)&Vs[j * PAD + (t * 4 + c) * 4];
                acc4[t].x += p * vv.x; acc4[t].y += p * vv.y;
                acc4[t].z += p * vv.z; acc4[t].w += p * vv.w;
            }
        }
        __syncthreads();
    }

    if (sq < S_) {
        float inv = 1.0f / l_i;
        float* op = g_ctx + ((size_t)b * S_ + sq) * E_ + h * 64;
#pragma unroll
        for (int t = 0; t < 4; t++) {
            float4 r;
            r.x = acc4[t].x * inv; r.y = acc4[t].y * inv;
            r.z = acc4[t].z * inv; r.w = acc4[t].w * inv;
            *(float4*)(op + (t * 4 + c) * 4) = r;
        }
    }
}

// ---------------------------------------------------------------------------
extern "C" void kernel_launch(void* const* d_in, const int* in_sizes, int n_in,
                              void* d_out, int out_size)
{
    const float* x    = (const float*)d_in[0];  // hidden_states [4,1500,1280]
    const float* mask = (const float*)d_in[1];  // attention_mask [4,1,1500,1500]
    const float* Wq   = (const float*)d_in[2];
    const float* bq   = (const float*)d_in[3];
    const float* Wk   = (const float*)d_in[4];
    const float* Wv   = (const float*)d_in[5];
    const float* bv   = (const float*)d_in[6];
    const float* Wo   = (const float*)d_in[7];
    const float* bo   = (const float*)d_in[8];
    float* out = (float*)d_out;

    const float scale = 0.125f;  // HEAD_DIM^-0.5

    cudaFuncSetAttribute(attn_kernel,
                         cudaFuncAttributeMaxDynamicSharedMemorySize, ATTN_SMEM);

    dim3 ggrid((M_ + 127) / 128, E_ / 128);   // (47, 10)
    gemm128<<<ggrid, 256>>>(x, Wq, bq, scale, nullptr, 1);   // -> g_q
    gemm128<<<ggrid, 256>>>(x, Wk, nullptr, 1.f, nullptr, 2); // -> g_k
    gemm128<<<ggrid, 256>>>(x, Wv, bv, 1.f, nullptr, 3);     // -> g_v

    dim3 agrid((S_ + 63) / 64, B_ * H_);      // (24, 80)
    attn_kernel<<<agrid, 256, ATTN_SMEM>>>(mask);            // -> g_ctx

    gemm128<<<ggrid, 256>>>(nullptr, Wo, bo, 1.f, out, 0);   // g_ctx -> out
}

// round 7
// speedup vs baseline: 1.0006x; 1.0006x over previous
#include <cuda_runtime.h>
#include <cuda_bf16.h>
#include <math.h>

// Problem constants
#define B_   4
#define S_   1500
#define E_   1280
#define H_   20
#define D_   64
#define M_   (B_ * S_)   // 6000

// Scratch buffers (device globals: allocation-free rule)
__device__ float g_q[(size_t)B_ * H_ * S_ * D_];    // [b,h,s,d]
__device__ float g_k[(size_t)B_ * H_ * S_ * D_];
__device__ float g_v[(size_t)B_ * H_ * S_ * D_];
__device__ float g_ctx[(size_t)B_ * S_ * E_];       // [b,s,(h*64+d)]

// ---------------------------------------------------------------------------
// Generic 128x128x16 SIMT fp32 GEMM:  out = A[M,K] @ W[N,K]^T  (+bias)(*scale)
// mode 0: plain row-major [M,N] out, +bias              (final projection)
// mode 1: scatter to g_q [b,h,s,d], (+bias)*scale       (q projection)
// mode 2: scatter to g_k [b,h,s,d], no bias             (k projection)
// mode 3: scatter to g_v [b,h,s,d], +bias               (v projection)
// A==nullptr means "read from g_ctx".
// ---------------------------------------------------------------------------
__global__ void gemm128(const float* __restrict__ A,
                        const float* __restrict__ W,
                        const float* __restrict__ bias,
                        float scale,
                        float* __restrict__ out,
                        int mode)
{
    const int K = E_;
    const int N = E_;
    __shared__ float As[16][128];
    __shared__ float Bs[16][128];

    const float* Ap = A ? A : g_ctx;

    int tid = threadIdx.x;
    int m0 = blockIdx.x * 128;
    int n0 = blockIdx.y * 128;
    int tx = tid & 15;          // 0..15
    int ty = tid >> 4;          // 0..15

    float acc[8][8];
#pragma unroll
    for (int i = 0; i < 8; i++)
#pragma unroll
        for (int j = 0; j < 8; j++) acc[i][j] = 0.f;

    int lr = tid >> 2;           // 0..63
    int lc4 = (tid & 3) * 4;     // 0,4,8,12

    for (int k0 = 0; k0 < K; k0 += 16) {
#pragma unroll
        for (int half = 0; half < 2; half++) {
            int row = lr + half * 64;
            int gm = m0 + row;
            float4 av = make_float4(0.f, 0.f, 0.f, 0.f);
            if (gm < M_)
                av = *(const float4*)(Ap + (size_t)gm * K + k0 + lc4);
            As[lc4 + 0][row] = av.x;
            As[lc4 + 1][row] = av.y;
            As[lc4 + 2][row] = av.z;
            As[lc4 + 3][row] = av.w;

            int gn = n0 + row;   // always < 1280
            float4 bv = *(const float4*)(W + (size_t)gn * K + k0 + lc4);
            Bs[lc4 + 0][row] = bv.x;
            Bs[lc4 + 1][row] = bv.y;
            Bs[lc4 + 2][row] = bv.z;
            Bs[lc4 + 3][row] = bv.w;
        }
        __syncthreads();

#pragma unroll
        for (int kk = 0; kk < 16; kk++) {
            float4 a0 = *(const float4*)&As[kk][ty * 8];
            float4 a1 = *(const float4*)&As[kk][ty * 8 + 4];
            float4 b0 = *(const float4*)&Bs[kk][tx * 8];
            float4 b1 = *(const float4*)&Bs[kk][tx * 8 + 4];
            float a[8] = {a0.x, a0.y, a0.z, a0.w, a1.x, a1.y, a1.z, a1.w};
            float b[8] = {b0.x, b0.y, b0.z, b0.w, b1.x, b1.y, b1.z, b1.w};
#pragma unroll
            for (int i = 0; i < 8; i++)
#pragma unroll
                for (int j = 0; j < 8; j++)
                    acc[i][j] += a[i] * b[j];
        }
        __syncthreads();
    }

    // epilogue
    float* qout = g_q;
    float* kout = g_k;
    float* vout = g_v;
#pragma unroll
    for (int i = 0; i < 8; i++) {
        int gm = m0 + ty * 8 + i;
        if (gm >= M_) continue;
        int b = gm / S_;
        int s = gm % S_;
#pragma unroll
        for (int j = 0; j < 8; j++) {
            int gn = n0 + tx * 8 + j;
            float v = acc[i][j];
            if (mode == 0) {
                out[(size_t)gm * N + gn] = v + bias[gn];
            } else {
                if (mode == 1) v = (v + bias[gn]) * scale;
                else if (mode == 3) v = v + bias[gn];
                int h = gn >> 6;
                int d = gn & 63;
                size_t idx = ((((size_t)b * H_ + h) * S_) + s) * D_ + d;
                if (mode == 1) qout[idx] = v;
                else if (mode == 2) kout[idx] = v;
                else vout[idx] = v;
            }
        }
    }
}

// ---------------------------------------------------------------------------
// Flash attention: grid (qblocks=24, bh=80), 256 threads.
// 64 query rows x 64 key cols per tile; online softmax; context written in
// [b, s, h*64+d] layout so the output GEMM reads it row-major.
// Shared tiles padded to stride 68 floats => all inner-loop LDS.128
// conflict-free, and 16B-aligned rows.
// ---------------------------------------------------------------------------
#define PAD 68
#define ATTN_SMEM (4 * 64 * PAD * 4)   // 69632 bytes

__global__ void attn_kernel(const float* __restrict__ mask)
{
    extern __shared__ float sm[];
    float* Qs = sm;                     // [64][68]
    float* Ks = sm + 64 * PAD;
    float* Vs = sm + 2 * 64 * PAD;
    float* Ps = sm + 3 * 64 * PAD;

    int bh = blockIdx.y;
    int b = bh / H_;
    int h = bh % H_;
    int qb = blockIdx.x;
    int tid = threadIdx.x;
    int i = tid >> 2;      // query row within tile, 0..63
    int c = tid & 3;       // 0..3

    const float* qbase = g_q + (((size_t)b * H_ + h) * S_) * D_;
    const float* kbase = g_k + (((size_t)b * H_ + h) * S_) * D_;
    const float* vbase = g_v + (((size_t)b * H_ + h) * S_) * D_;

    // load Q tile
    {
        int lr = tid >> 4;           // 0..15
        int lc = (tid & 15) * 4;     // 0..60
        for (int r = lr; r < 64; r += 16) {
            int sq = qb * 64 + r;
            float4 val = make_float4(0.f, 0.f, 0.f, 0.f);
            if (sq < S_)
                val = *(const float4*)(qbase + (size_t)sq * D_ + lc);
            Qs[r * PAD + lc + 0] = val.x;
            Qs[r * PAD + lc + 1] = val.y;
            Qs[r * PAD + lc + 2] = val.z;
            Qs[r * PAD + lc + 3] = val.w;
        }
    }

    float4 acc4[4];
#pragma unroll
    for (int t = 0; t < 4; t++) acc4[t] = make_float4(0.f, 0.f, 0.f, 0.f);
    float m_i = -1e30f, l_i = 0.f;

    int sq = qb * 64 + i;
    const float* mrow = mask + ((size_t)b * S_ + (sq < S_ ? sq : S_ - 1)) * S_;

    const int nkb = (S_ + 63) / 64;   // 24
    for (int kb = 0; kb < nkb; kb++) {
        // load K/V tiles
        {
            int lr = tid >> 4;
            int lc = (tid & 15) * 4;
            for (int r = lr; r < 64; r += 16) {
                int sk = kb * 64 + r;
                float4 kv = make_float4(0.f, 0.f, 0.f, 0.f);
                float4 vv = make_float4(0.f, 0.f, 0.f, 0.f);
                if (sk < S_) {
                    kv = *(const float4*)(kbase + (size_t)sk * D_ + lc);
                    vv = *(const float4*)(vbase + (size_t)sk * D_ + lc);
                }
                Ks[r * PAD + lc + 0] = kv.x; Ks[r * PAD + lc + 1] = kv.y;
                Ks[r * PAD + lc + 2] = kv.z; Ks[r * PAD + lc + 3] = kv.w;
                Vs[r * PAD + lc + 0] = vv.x; Vs[r * PAD + lc + 1] = vv.y;
                Vs[r * PAD + lc + 2] = vv.z; Vs[r * PAD + lc + 3] = vv.w;
            }
        }
        __syncthreads();

        // scores: thread (i,c) computes keys j = jj*4 + c, jj = 0..15
        float sc[16];
#pragma unroll
        for (int jj = 0; jj < 16; jj++) sc[jj] = 0.f;
#pragma unroll
        for (int d4 = 0; d4 < 16; d4++) {
            float4 qa = *(const float4*)&Qs[i * PAD + d4 * 4];
#pragma unroll
            for (int jj = 0; jj < 16; jj++) {
                float4 kk4 = *(const float4*)&Ks[(jj * 4 + c) * PAD + d4 * 4];
                sc[jj] += qa.x * kk4.x + qa.y * kk4.y + qa.z * kk4.z + qa.w * kk4.w;
            }
        }
        // add mask / bound keys
#pragma unroll
        for (int jj = 0; jj < 16; jj++) {
            int sk = kb * 64 + jj * 4 + c;
            sc[jj] = (sk < S_) ? (sc[jj] + mrow[sk]) : -1e30f;
        }

        // online softmax (row groups of 4 lanes)
        float rmax = sc[0];
#pragma unroll
        for (int jj = 1; jj < 16; jj++) rmax = fmaxf(rmax, sc[jj]);
        rmax = fmaxf(rmax, __shfl_xor_sync(0xffffffffu, rmax, 1));
        rmax = fmaxf(rmax, __shfl_xor_sync(0xffffffffu, rmax, 2));
        float mnew = fmaxf(m_i, rmax);
        float corr = __expf(m_i - mnew);
        float rsum = 0.f;
#pragma unroll
        for (int jj = 0; jj < 16; jj++) {
            float p = __expf(sc[jj] - mnew);
            Ps[i * PAD + jj * 4 + c] = p;
            rsum += p;
        }
        rsum += __shfl_xor_sync(0xffffffffu, rsum, 1);
        rsum += __shfl_xor_sync(0xffffffffu, rsum, 2);
        l_i = l_i * corr + rsum;
        m_i = mnew;
#pragma unroll
        for (int t = 0; t < 4; t++) {
            acc4[t].x *= corr; acc4[t].y *= corr;
            acc4[t].z *= corr; acc4[t].w *= corr;
        }
        __syncthreads();

        // AV: thread (i,c) owns d-chunks (t*4+c)*4 .. +3
        for (int j = 0; j < 64; j++) {
            float p = Ps[i * PAD + j];
#pragma unroll
            for (int t = 0; t < 4; t++) {
                float4 vv = *(const float4*)&Vs[j * PAD + (t * 4 + c) * 4];
                acc4[t].x += p * vv.x; acc4[t].y += p * vv.y;
                acc4[t].z += p * vv.z; acc4[t].w += p * vv.w;
            }
        }
        __syncthreads();
    }

    if (sq < S_) {
        float inv = 1.0f / l_i;
        float* op = g_ctx + ((size_t)b * S_ + sq) * E_ + h * 64;
#pragma unroll
        for (int t = 0; t < 4; t++) {
            float4 r;
            r.x = acc4[t].x * inv; r.y = acc4[t].y * inv;
            r.z = acc4[t].z * inv; r.w = acc4[t].w * inv;
            *(float4*)(op + (t * 4 + c) * 4) = r;
        }
    }
}

// ---------------------------------------------------------------------------
extern "C" void kernel_launch(void* const* d_in, const int* in_sizes, int n_in,
                              void* d_out, int out_size)
{
    const float* x    = (const float*)d_in[0];  // hidden_states [4,1500,1280]
    const float* mask = (const float*)d_in[1];  // attention_mask [4,1,1500,1500]
    const float* Wq   = (const float*)d_in[2];
    const float* bq   = (const float*)d_in[3];
    const float* Wk   = (const float*)d_in[4];
    const float* Wv   = (const float*)d_in[5];
    const float* bv   = (const float*)d_in[6];
    const float* Wo   = (const float*)d_in[7];
    const float* bo   = (const float*)d_in[8];
    float* out = (float*)d_out;

    const float scale = 0.125f;  // HEAD_DIM^-0.5

    cudaFuncSetAttribute(attn_kernel,
                         cudaFuncAttributeMaxDynamicSharedMemorySize, ATTN_SMEM);

    dim3 ggrid((M_ + 127) / 128, E_ / 128);   // (47, 10)
    gemm128<<<ggrid, 256>>>(x, Wq, bq, scale, nullptr, 1);   // -> g_q
    gemm128<<<ggrid, 256>>>(x, Wk, nullptr, 1.f, nullptr, 2); // -> g_k
    gemm128<<<ggrid, 256>>>(x, Wv, bv, 1.f, nullptr, 3);     // -> g_v

    dim3 agrid((S_ + 63) / 64, B_ * H_);      // (24, 80)
    attn_kernel<<<agrid, 256, ATTN_SMEM>>>(mask);            // -> g_ctx

    gemm128<<<ggrid, 256>>>(nullptr, Wo, bo, 1.f, out, 0);   // g_ctx -> out
}

// round 8
// speedup vs baseline: 3.1624x; 3.1605x over previous
#include <cuda_runtime.h>
#include <cuda_bf16.h>
#include <stdint.h>
#include <math.h>

#define B_ 4
#define S_ 1500
#define SP_ 1504
#define E_ 1280
#define H_ 20
#define D_ 64
#define M_ 6000
#define GS 24
#define AS 72

__device__ __align__(128) __nv_bfloat16 g_qh[(size_t)B_*H_*S_*D_];
__device__ __align__(128) __nv_bfloat16 g_ql[(size_t)B_*H_*S_*D_];
__device__ __align__(128) __nv_bfloat16 g_kh[(size_t)B_*H_*S_*D_];
__device__ __align__(128) __nv_bfloat16 g_kl[(size_t)B_*H_*S_*D_];
__device__ __align__(128) __nv_bfloat16 g_vth[(size_t)B_*H_*D_*SP_];
__device__ __align__(128) __nv_bfloat16 g_vtl[(size_t)B_*H_*D_*SP_];
__device__ __align__(128) float g_ctx[(size_t)M_*E_];

__device__ __forceinline__ uint32_t sptr(const void* p) {
    return (uint32_t)__cvta_generic_to_shared(p);
}
__device__ __forceinline__ void ldsm4(uint32_t* r, uint32_t a) {
    asm volatile("ldmatrix.sync.aligned.m8n8.x4.shared.b16 {%0,%1,%2,%3},[%4];"
                 : "=r"(r[0]), "=r"(r[1]), "=r"(r[2]), "=r"(r[3]) : "r"(a));
}
__device__ __forceinline__ void mma16816(float* c, const uint32_t* a,
                                         uint32_t b0, uint32_t b1) {
    asm volatile(
        "mma.sync.aligned.m16n8k16.row.col.f32.bf16.bf16.f32 "
        "{%0,%1,%2,%3},{%4,%5,%6,%7},{%8,%9},{%0,%1,%2,%3};"
        : "+f"(c[0]), "+f"(c[1]), "+f"(c[2]), "+f"(c[3])
        : "r"(a[0]), "r"(a[1]), "r"(a[2]), "r"(a[3]), "r"(b0), "r"(b1));
}
__device__ __forceinline__ void split_pack(float x, float y, uint32_t& hi, uint32_t& lo) {
    __nv_bfloat16 hx = __float2bfloat16_rn(x), hy = __float2bfloat16_rn(y);
    __nv_bfloat16 lx = __float2bfloat16_rn(x - __bfloat162float(hx));
    __nv_bfloat16 ly = __float2bfloat16_rn(y - __bfloat162float(hy));
    __nv_bfloat162 hh; hh.x = hx; hh.y = hy;
    __nv_bfloat162 ll; ll.x = lx; ll.y = ly;
    hi = *reinterpret_cast<uint32_t*>(&hh);
    lo = *reinterpret_cast<uint32_t*>(&ll);
}

// 128x128x32-tile split-bf16 tensor GEMM: out = A[M,1280] @ W[1280,1280]^T
// mode 0: fp32 [M,N] + bias (A = g_ctx). mode 1: ->q hi/lo, (+b)*0.125.
// mode 2: ->k hi/lo. mode 3: ->v^T hi/lo [b,h,d,s] (+b).
__global__ __launch_bounds__(256) void gemm_tc(
    const float* __restrict__ A, const float* __restrict__ W,
    const float* __restrict__ bias, float* __restrict__ out, int mode)
{
    extern __shared__ __nv_bfloat16 dsm[];
    __nv_bfloat16* sA = dsm;             // [kc2(2)][hl(2)]x128xGS
    __nv_bfloat16* sB = dsm + 4*128*GS;

    const float* Ap = A ? A : g_ctx;
    int tid = threadIdx.x, lane = tid & 31, warp = tid >> 5;
    int m0 = blockIdx.x * 128, n0 = blockIdx.y * 128;
    int wm = (warp >> 1) * 32, wn = (warp & 1) * 64;

    float acc[2][8][4];
#pragma unroll
    for (int a = 0; a < 2; a++)
#pragma unroll
        for (int nb = 0; nb < 8; nb++)
#pragma unroll
            for (int r = 0; r < 4; r++) acc[a][nb][r] = 0.f;

    int lrow = tid >> 1, lch = tid & 1;
    bool mok = (m0 + lrow) < M_;
    const float* agp = Ap + (size_t)(m0 + lrow) * E_ + lch * 16;
    const float* bgp = W  + (size_t)(n0 + lrow) * E_ + lch * 16;

    float4 fa[4], fb[4];
#pragma unroll
    for (int i = 0; i < 4; i++) {
        fa[i] = mok ? *(const float4*)(agp + i*4) : make_float4(0.f,0.f,0.f,0.f);
        fb[i] = *(const float4*)(bgp + i*4);
    }

    const int NK = E_ / 32;
    for (int kc = 0; kc < NK; kc++) {
        __syncthreads();
#pragma unroll
        for (int i = 0; i < 4; i++) {
            uint32_t h01, l01, h23, l23;
            int bhx = (lch*2+0)*128*GS + lrow*GS + i*4;
            int blx = (lch*2+1)*128*GS + lrow*GS + i*4;
            split_pack(fa[i].x, fa[i].y, h01, l01);
            split_pack(fa[i].z, fa[i].w, h23, l23);
            *(uint32_t*)&sA[bhx] = h01; *(uint32_t*)&sA[bhx+2] = h23;
            *(uint32_t*)&sA[blx] = l01; *(uint32_t*)&sA[blx+2] = l23;
            split_pack(fb[i].x, fb[i].y, h01, l01);
            split_pack(fb[i].z, fb[i].w, h23, l23);
            *(uint32_t*)&sB[bhx] = h01; *(uint32_t*)&sB[bhx+2] = h23;
            *(uint32_t*)&sB[blx] = l01; *(uint32_t*)&sB[blx+2] = l23;
        }
        __syncthreads();
        if (kc + 1 < NK) {
#pragma unroll
            for (int i = 0; i < 4; i++) {
                fa[i] = mok ? *(const float4*)(agp + (kc+1)*32 + i*4)
                            : make_float4(0.f,0.f,0.f,0.f);
                fb[i] = *(const float4*)(bgp + (kc+1)*32 + i*4);
            }
        }
#pragma unroll
        for (int cc = 0; cc < 2; cc++) {
            uint32_t ah[2][4], al[2][4];
            int arow = wm + (lane & 7) + ((lane >> 3) & 1) * 8;
            int akof = (lane >> 4) * 8;
#pragma unroll
            for (int a = 0; a < 2; a++) {
                ldsm4(ah[a], sptr(&sA[(cc*2+0)*128*GS + (arow+a*16)*GS + akof]));
                ldsm4(al[a], sptr(&sA[(cc*2+1)*128*GS + (arow+a*16)*GS + akof]));
            }
            int brow = wn + (lane & 7) + (lane >> 4) * 8;
            int bkof = ((lane >> 3) & 1) * 8;
            uint32_t bh[4][4], bl[4][4];
#pragma unroll
            for (int p = 0; p < 4; p++) {
                ldsm4(bh[p], sptr(&sB[(cc*2+0)*128*GS + (brow+p*16)*GS + bkof]));
                ldsm4(bl[p], sptr(&sB[(cc*2+1)*128*GS + (brow+p*16)*GS + bkof]));
            }
#pragma unroll
            for (int a = 0; a < 2; a++)
#pragma unroll
                for (int nb = 0; nb < 8; nb++) {
                    uint32_t b0h = bh[nb>>1][(nb&1)*2], b1h = bh[nb>>1][(nb&1)*2+1];
                    uint32_t b0l = bl[nb>>1][(nb&1)*2], b1l = bl[nb>>1][(nb&1)*2+1];
                    mma16816(acc[a][nb], ah[a], b0h, b1h);
                    mma16816(acc[a][nb], ah[a], b0l, b1l);
                    mma16816(acc[a][nb], al[a], b0h, b1h);
                }
        }
    }

#pragma unroll
    for (int a = 0; a < 2; a++)
#pragma unroll
        for (int rr = 0; rr < 2; rr++) {
            int gm = m0 + wm + a*16 + (lane >> 2) + rr*8;
            if (gm >= M_) continue;
            int bb = gm / S_, ss = gm % S_;
#pragma unroll
            for (int nb = 0; nb < 8; nb++) {
                int n = n0 + wn + nb*8 + (lane & 3)*2;
                float v0 = acc[a][nb][rr*2+0], v1 = acc[a][nb][rr*2+1];
                if (mode == 0) {
                    float2 o; o.x = v0 + bias[n]; o.y = v1 + bias[n+1];
                    *(float2*)&out[(size_t)gm*E_ + n] = o;
                } else {
                    if (mode == 1) { v0 = (v0+bias[n])*0.125f; v1 = (v1+bias[n+1])*0.125f; }
                    else if (mode == 3) { v0 += bias[n]; v1 += bias[n+1]; }
                    int hh = n >> 6, dd = n & 63;
                    uint32_t hi, lo;
                    split_pack(v0, v1, hi, lo);
                    if (mode == 3) {
                        size_t base = (((size_t)bb*H_ + hh)*D_ + dd)*SP_ + ss;
                        __nv_bfloat162 Hh = *(__nv_bfloat162*)&hi;
                        __nv_bfloat162 Ll = *(__nv_bfloat162*)&lo;
                        g_vth[base] = Hh.x; g_vth[base+SP_] = Hh.y;
                        g_vtl[base] = Ll.x; g_vtl[base+SP_] = Ll.y;
                    } else {
                        size_t idx = (((size_t)bb*H_ + hh)*S_ + ss)*D_ + dd;
                        if (mode == 1) { *(uint32_t*)&g_qh[idx] = hi; *(uint32_t*)&g_ql[idx] = lo; }
                        else           { *(uint32_t*)&g_kh[idx] = hi; *(uint32_t*)&g_kl[idx] = lo; }
                    }
                }
            }
        }
}

// Tensor-core flash attention: 128 thr (4 warps x 16 q-rows = 64 q), 64-key
// chunks, online softmax on register fragments, in-register P repack for P@V.
__global__ __launch_bounds__(128) void attn_tc(const float* __restrict__ mask)
{
    __shared__ __align__(16) __nv_bfloat16 sK[2*64*AS];
    __shared__ __align__(16) __nv_bfloat16 sV[2*64*AS];

    int tid = threadIdx.x, lane = tid & 31, warp = tid >> 5;
    int qb = blockIdx.x, bh = blockIdx.y;
    int b = bh / H_;
    const __nv_bfloat16* qhp = g_qh  + (size_t)bh*S_*D_;
    const __nv_bfloat16* qlp = g_ql  + (size_t)bh*S_*D_;
    const __nv_bfloat16* khp = g_kh  + (size_t)bh*S_*D_;
    const __nv_bfloat16* klp = g_kl  + (size_t)bh*S_*D_;
    const __nv_bfloat16* vhp = g_vth + (size_t)bh*D_*SP_;
    const __nv_bfloat16* vlp = g_vtl + (size_t)bh*D_*SP_;
    int s0q = qb * 64;

    // stage Q (hi/lo) via sK, build persistent A fragments
#pragma unroll
    for (int it = 0; it < 8; it++) {
        int idx = it*128 + tid;
        int hl = idx >> 9, r = (idx >> 3) & 63, c8 = idx & 7;
        const __nv_bfloat16* src = hl ? qlp : qhp;
        uint4 v = make_uint4(0u,0u,0u,0u);
        if (s0q + r < S_) v = *(const uint4*)(src + (size_t)(s0q+r)*D_ + c8*8);
        *(uint4*)&sK[hl*64*AS + r*AS + c8*8] = v;
    }
    __syncthreads();

    uint32_t qf[2][4][4];
    {
        int arow = warp*16 + (lane & 7) + ((lane >> 3) & 1)*8;
        int akof = (lane >> 4)*8;
#pragma unroll
        for (int hl = 0; hl < 2; hl++)
#pragma unroll
            for (int kb = 0; kb < 4; kb++)
                ldsm4(qf[hl][kb], sptr(&sK[hl*64*AS + arow*AS + kb*16 + akof]));
    }
    __syncthreads();

    float oacc[8][4];
#pragma unroll
    for (int d = 0; d < 8; d++)
#pragma unroll
        for (int r = 0; r < 4; r++) oacc[d][r] = 0.f;
    float mi0 = -1e30f, mi1 = -1e30f, li0 = 0.f, li1 = 0.f;

    int r0 = warp*16 + (lane >> 2);
    int sq0 = s0q + r0, sq1 = sq0 + 8;
    const float* mrow0 = mask + ((size_t)b*S_ + (sq0 < S_ ? sq0 : S_-1))*S_;
    const float* mrow1 = mask + ((size_t)b*S_ + (sq1 < S_ ? sq1 : S_-1))*S_;

    const int NC = (S_ + 63) / 64;   // 24
    for (int kc = 0; kc < NC; kc++) {
        int s0 = kc * 64;
        if (s0 + 64 <= S_) {
#pragma unroll
            for (int it = 0; it < 8; it++) {
                int idx = it*128 + tid;
                int hl = idx >> 9, r = (idx >> 3) & 63, c8 = idx & 7;
                const __nv_bfloat16* ks = hl ? klp : khp;
                const __nv_bfloat16* vs = hl ? vlp : vhp;
                *(uint4*)&sK[hl*64*AS + r*AS + c8*8] =
                    *(const uint4*)(ks + (size_t)(s0+r)*D_ + c8*8);
                *(uint4*)&sV[hl*64*AS + r*AS + c8*8] =
                    *(const uint4*)(vs + (size_t)r*SP_ + s0 + c8*8);
            }
        } else {
#pragma unroll
            for (int it = 0; it < 8; it++) {
                int idx = it*128 + tid;
                int hl = idx >> 9, r = (idx >> 3) & 63, c8 = idx & 7;
                const __nv_bfloat16* ks = hl ? klp : khp;
                const __nv_bfloat16* vs = hl ? vlp : vhp;
                uint4 kv = make_uint4(0u,0u,0u,0u);
                if (s0 + r < S_) kv = *(const uint4*)(ks + (size_t)(s0+r)*D_ + c8*8);
                *(uint4*)&sK[hl*64*AS + r*AS + c8*8] = kv;
                uint4 vv; __nv_bfloat16* tp = (__nv_bfloat16*)&vv;
#pragma unroll
                for (int e = 0; e < 8; e++) {
                    int s = s0 + c8*8 + e;
                    tp[e] = (s < S_) ? vs[(size_t)r*SP_ + s] : __float2bfloat16_rn(0.f);
                }
                *(uint4*)&sV[hl*64*AS + r*AS + c8*8] = vv;
            }
        }
        __syncthreads();

        // S = Q @ K^T (3-pass split)
        float sc[8][4];
#pragma unroll
        for (int nb = 0; nb < 8; nb++)
#pragma unroll
            for (int r = 0; r < 4; r++) sc[nb][r] = 0.f;
        {
            int brow = (lane & 7) + (lane >> 4)*8;
            int bkof = ((lane >> 3) & 1)*8;
#pragma unroll
            for (int kb = 0; kb < 4; kb++) {
                uint32_t khf[4][4], klf[4][4];
#pragma unroll
                for (int p = 0; p < 4; p++) {
                    ldsm4(khf[p], sptr(&sK[0*64*AS + (brow+p*16)*AS + kb*16 + bkof]));
                    ldsm4(klf[p], sptr(&sK[1*64*AS + (brow+p*16)*AS + kb*16 + bkof]));
                }
#pragma unroll
                for (int nb = 0; nb < 8; nb++) {
                    uint32_t b0h = khf[nb>>1][(nb&1)*2], b1h = khf[nb>>1][(nb&1)*2+1];
                    uint32_t b0l = klf[nb>>1][(nb&1)*2], b1l = klf[nb>>1][(nb&1)*2+1];
                    mma16816(sc[nb], qf[0][kb], b0h, b1h);
                    mma16816(sc[nb], qf[0][kb], b0l, b1l);
                    mma16816(sc[nb], qf[1][kb], b0h, b1h);
                }
            }
        }

        // mask + online softmax
        float mnew0 = mi0, mnew1 = mi1;
        int colb = s0 + (lane & 3)*2;
#pragma unroll
        for (int nb = 0; nb < 8; nb++) {
            int col = colb + nb*8;
            float2 mk0 = make_float2(-1e30f, -1e30f), mk1 = mk0;
            if (col < S_) { mk0 = *(const float2*)(mrow0 + col);
                            mk1 = *(const float2*)(mrow1 + col); }
            sc[nb][0] += mk0.x; sc[nb][1] += mk0.y;
            sc[nb][2] += mk1.x; sc[nb][3] += mk1.y;
            mnew0 = fmaxf(mnew0, fmaxf(sc[nb][0], sc[nb][1]));
            mnew1 = fmaxf(mnew1, fmaxf(sc[nb][2], sc[nb][3]));
        }
        mnew0 = fmaxf(mnew0, __shfl_xor_sync(0xffffffffu, mnew0, 1));
        mnew0 = fmaxf(mnew0, __shfl_xor_sync(0xffffffffu, mnew0, 2));
        mnew1 = fmaxf(mnew1, __shfl_xor_sync(0xffffffffu, mnew1, 1));
        mnew1 = fmaxf(mnew1, __shfl_xor_sync(0xffffffffu, mnew1, 2));
        float corr0 = __expf(mi0 - mnew0), corr1 = __expf(mi1 - mnew1);
        float rs0 = 0.f, rs1 = 0.f;
#pragma unroll
        for (int nb = 0; nb < 8; nb++) {
            sc[nb][0] = __expf(sc[nb][0] - mnew0);
            sc[nb][1] = __expf(sc[nb][1] - mnew0);
            sc[nb][2] = __expf(sc[nb][2] - mnew1);
            sc[nb][3] = __expf(sc[nb][3] - mnew1);
            rs0 += sc[nb][0] + sc[nb][1];
            rs1 += sc[nb][2] + sc[nb][3];
        }
        rs0 += __shfl_xor_sync(0xffffffffu, rs0, 1);
        rs0 += __shfl_xor_sync(0xffffffffu, rs0, 2);
        rs1 += __shfl_xor_sync(0xffffffffu, rs1, 1);
        rs1 += __shfl_xor_sync(0xffffffffu, rs1, 2);
        li0 = li0*corr0 + rs0; li1 = li1*corr1 + rs1;
        mi0 = mnew0; mi1 = mnew1;
#pragma unroll
        for (int d = 0; d < 8; d++) {
            oacc[d][0] *= corr0; oacc[d][1] *= corr0;
            oacc[d][2] *= corr1; oacc[d][3] *= corr1;
        }

        // O += P @ V (P fragments repacked in-register, 3-pass split)
        {
            int brow = (lane & 7) + (lane >> 4)*8;
            int bkof = ((lane >> 3) & 1)*8;
#pragma unroll
            for (int kb = 0; kb < 4; kb++) {
                uint32_t ph[4], pl[4];
                split_pack(sc[2*kb][0],   sc[2*kb][1],   ph[0], pl[0]);
                split_pack(sc[2*kb][2],   sc[2*kb][3],   ph[1], pl[1]);
                split_pack(sc[2*kb+1][0], sc[2*kb+1][1], ph[2], pl[2]);
                split_pack(sc[2*kb+1][2], sc[2*kb+1][3], ph[3], pl[3]);
                uint32_t vhf[4][4], vlf[4][4];
#pragma unroll
                for (int p = 0; p < 4; p++) {
                    ldsm4(vhf[p], sptr(&sV[0*64*AS + (brow+p*16)*AS + kb*16 + bkof]));
                    ldsm4(vlf[p], sptr(&sV[1*64*AS + (brow+p*16)*AS + kb*16 + bkof]));
                }
#pragma unroll
                for (int db = 0; db < 8; db++) {
                    uint32_t b0h = vhf[db>>1][(db&1)*2], b1h = vhf[db>>1][(db&1)*2+1];
                    uint32_t b0l = vlf[db>>1][(db&1)*2], b1l = vlf[db>>1][(db&1)*2+1];
                    mma16816(oacc[db], ph, b0h, b1h);
                    mma16816(oacc[db], ph, b0l, b1l);
                    mma16816(oacc[db], pl, b0h, b1h);
                }
            }
        }
        __syncthreads();
    }

    float inv0 = 1.f/li0, inv1 = 1.f/li1;
    int hcol = (bh % H_) * 64;
#pragma unroll
    for (int db = 0; db < 8; db++) {
        int col = hcol + db*8 + (lane & 3)*2;
        if (sq0 < S_) {
            float2 o; o.x = oacc[db][0]*inv0; o.y = oacc[db][1]*inv0;
            *(float2*)&g_ctx[((size_t)b*S_ + sq0)*E_ + col] = o;
        }
        if (sq1 < S_) {
            float2 o; o.x = oacc[db][2]*inv1; o.y = oacc[db][3]*inv1;
            *(float2*)&g_ctx[((size_t)b*S_ + sq1)*E_ + col] = o;
        }
    }
}

extern "C" void kernel_launch(void* const* d_in, const int* in_sizes, int n_in,
                              void* d_out, int out_size)
{
    const float* x    = (const float*)d_in[0];
    const float* mask = (const float*)d_in[1];
    const float* Wq   = (const float*)d_in[2];
    const float* bq   = (const float*)d_in[3];
    const float* Wk   = (const float*)d_in[4];
    const float* Wv   = (const float*)d_in[5];
    const float* bv   = (const float*)d_in[6];
    const float* Wo   = (const float*)d_in[7];
    const float* bo   = (const float*)d_in[8];
    float* out = (float*)d_out;

    const int GSMEM = 8 * 128 * GS * (int)sizeof(__nv_bfloat16);  // 49152 B
    cudaFuncSetAttribute(gemm_tc, cudaFuncAttributeMaxDynamicSharedMemorySize, GSMEM);

    dim3 ggrid((M_ + 127) / 128, E_ / 128);          // (47, 10)
    gemm_tc<<<ggrid, 256, GSMEM>>>(x, Wq, bq, nullptr, 1);
    gemm_tc<<<ggrid, 256, GSMEM>>>(x, Wk, nullptr, nullptr, 2);
    gemm_tc<<<ggrid, 256, GSMEM>>>(x, Wv, bv, nullptr, 3);

    dim3 agrid((S_ + 63) / 64, B_ * H_);             // (24, 80)
    attn_tc<<<agrid, 128>>>(mask);

    gemm_tc<<<ggrid, 256, GSMEM>>>(nullptr, Wo, bo, out, 0);
}